// round 15
// baseline (speedup 1.0000x reference)
#include <cuda_runtime.h>

#define NFRAME 320
#define HOP    160
#define LAG    33
#define NTAU_OUT 224          // 257 - 33
#define FN     1000
#define SLEN   160000
#define EXT_LEN 576           // N + TAU - 1
#define EPS    1e-5f

#define WARPS_PER_BLK 4

typedef unsigned long long u64;

__device__ __forceinline__ u64 pk(float a, float b) {
    u64 r; asm("mov.b64 %0, {%1, %2};" : "=l"(r) : "f"(a), "f"(b)); return r;
}
__device__ __forceinline__ void fma2(u64& d, u64 a, u64 b) {
    asm("fma.rn.f32x2 %0, %1, %2, %0;" : "+l"(d) : "l"(a), "l"(b));
}
__device__ __forceinline__ float hadd2(u64 v) {
    float lo, hi;
    asm("mov.b64 {%0, %1}, %2;" : "=f"(lo), "=f"(hi) : "l"(v));
    return lo + hi;
}

// One WARP per (b, f). Lane computes 7 lags tau = 33 + 7*lane + k.
// f32x2 pairwise accumulation. Multiplier pairs arrive as broadcast LDS.128
// (ulonglong2 from E0/E1) whose components ARE the aligned b64 operands —
// no packing, 4 wide broadcasts per 8 samples instead of 8 narrow ones.
// E0 rows: 584 floats (2336 B, 16B-divisible). E1 rows: 588 floats (2352 B).
__global__ __launch_bounds__(32 * WARPS_PER_BLK)
void xcorr_kernel(const float* __restrict__ x, float* __restrict__ out)
{
    const int w    = threadIdx.x >> 5;
    const int lane = threadIdx.x & 31;
    const int bf   = blockIdx.x * WARPS_PER_BLK + w;
    const int b    = bf / FN;
    const int f    = bf % FN;
    const float* __restrict__ xb = x + (size_t)b * SLEN;

    __shared__ __align__(16) float sE0[WARPS_PER_BLK][EXT_LEN + 8];   // 584 f/row
    __shared__ __align__(16) float sE1[WARPS_PER_BLK][EXT_LEN + 12];  // 588 f/row
    __shared__ float sCs[WARPS_PER_BLK][EXT_LEN + 1];

    float* E0 = sE0[w];
    float* E1 = sE1[w];   // E1[j] = ext[j+1]
    float* cs = sCs[w];

    // ---- Load ext[576]: frame f (320) ++ first 256 of frame f+1 (wrap @ f=999) ----
    #pragma unroll
    for (int r = 0; r < 18; r++) {
        int j = lane + 32 * r;
        int idx;
        if (j < NFRAME)        idx = HOP * f + j;
        else if (f == FN - 1)  idx = j - NFRAME;           // wrap to frame 0
        else                   idx = HOP * f + j - HOP;    // frame f+1
        float v = (idx < SLEN) ? xb[idx] : 0.0f;           // zero-pad tail
        E0[j] = v;
        if (j > 0) E1[j - 1] = v;                          // shifted copy
    }
    if (lane < 8)  E0[EXT_LEN + lane] = 0.0f;              // E0[576..583] = 0
    if (lane < 13) E1[EXT_LEN - 1 + lane] = 0.0f;          // E1[575..587] = 0
    __syncwarp();

    // ---- Prefix sum of squares (per-warp): lane owns ext[18L .. 18L+17] ----
    {
        float loc[18];
        float s = 0.0f;
        #pragma unroll
        for (int i = 0; i < 18; i++) {
            float v = E0[18 * lane + i];
            s += v * v;
            loc[i] = s;
        }
        float v = s;
        #pragma unroll
        for (int d = 1; d < 32; d <<= 1) {
            float n = __shfl_up_sync(0xffffffffu, v, d);
            if (lane >= d) v += n;
        }
        float excl = v - s;
        if (lane == 0) cs[0] = 0.0f;
        #pragma unroll
        for (int i = 0; i < 18; i++)
            cs[18 * lane + 1 + i] = excl + loc[i];
    }
    __syncwarp();

    // ---- Main loop ----
    const int tau0 = LAG + 7 * lane;
    // wpair[i] = (ext[tau0+2i], ext[tau0+2i+1]) — 8B-aligned LDS.64
    const u64* wpair = (tau0 & 1) ? (const u64*)(E1 + (tau0 - 1))
                                  : (const u64*)(E0 + tau0);
    // m0v[i] covers E0[4i..4i+3]: .x=(ext[4i],ext[4i+1]) .y=(ext[4i+2],ext[4i+3])
    const ulonglong2* m0v = (const ulonglong2*)E0;
    // msv[i] covers E1[4i..4i+3]: .x=(ext[4i+1],ext[4i+2]) .y=(ext[4i+3],ext[4i+4])
    const ulonglong2* msv = (const ulonglong2*)E1;

    u64 d0 = wpair[0], d1 = wpair[1], d2 = wpair[2], d3 = wpair[3];
    const float c1 = E0[tau0 + 1], c3 = E0[tau0 + 3], c5 = E0[tau0 + 5];
    const float f0 = E0[0];

    u64 a0 = 0, a1 = 0, a2 = 0, a3 = 0, a4 = 0, a5 = 0, a6 = 0;

    #pragma unroll 4
    for (int g = 0; g < NFRAME / 8 - 1; g++) {   // groups 0..38 (8 samples each)
        const int h = 4 * g;
        ulonglong2 A = m0v[2 * g];       // mab pair0 = A.x, pair1 = A.y
        ulonglong2 B = m0v[2 * g + 1];   // mab pair2 = B.x, pair3 = B.y
        ulonglong2 S = msv[2 * g];       // mbc pair0 = S.x, pair1 = S.y
        ulonglong2 T = msv[2 * g + 1];   // mbc pair2 = T.x, pair3 = T.y

        // samples (8g, 8g+1)
        fma2(a0, A.x, d0); fma2(a2, A.x, d1); fma2(a4, A.x, d2); fma2(a6, A.x, d3);
        fma2(a1, S.x, d1); fma2(a3, S.x, d2); fma2(a5, S.x, d3);
        u64 d4 = wpair[h + 4];
        // samples (8g+2, 8g+3)
        fma2(a0, A.y, d1); fma2(a2, A.y, d2); fma2(a4, A.y, d3); fma2(a6, A.y, d4);
        fma2(a1, S.y, d2); fma2(a3, S.y, d3); fma2(a5, S.y, d4);
        u64 d5 = wpair[h + 5];
        // samples (8g+4, 8g+5)
        fma2(a0, B.x, d2); fma2(a2, B.x, d3); fma2(a4, B.x, d4); fma2(a6, B.x, d5);
        fma2(a1, T.x, d3); fma2(a3, T.x, d4); fma2(a5, T.x, d5);
        u64 d6 = wpair[h + 6];
        // samples (8g+6, 8g+7)
        fma2(a0, B.y, d3); fma2(a2, B.y, d4); fma2(a4, B.y, d5); fma2(a6, B.y, d6);
        fma2(a1, T.y, d4); fma2(a3, T.y, d5); fma2(a5, T.y, d6);
        u64 d7 = wpair[h + 7];

        d0 = d4; d1 = d5; d2 = d6; d3 = d7;
    }

    // ---- Peeled final group (g = 39, samples 312..319): fr[320] := 0 ----
    {
        const int g = 39, h = 4 * 39;
        ulonglong2 A = m0v[2 * g];
        ulonglong2 B = m0v[2 * g + 1];
        ulonglong2 S = msv[2 * g];
        ulonglong2 T = msv[2 * g + 1];
        u64 tfix = pk(E0[319], 0.0f);    // (fr[319], fr[320]=0) — only pack

        fma2(a0, A.x, d0); fma2(a2, A.x, d1); fma2(a4, A.x, d2); fma2(a6, A.x, d3);
        fma2(a1, S.x, d1); fma2(a3, S.x, d2); fma2(a5, S.x, d3);
        u64 d4 = wpair[h + 4];
        fma2(a0, A.y, d1); fma2(a2, A.y, d2); fma2(a4, A.y, d3); fma2(a6, A.y, d4);
        fma2(a1, S.y, d2); fma2(a3, S.y, d3); fma2(a5, S.y, d4);
        u64 d5 = wpair[h + 5];
        fma2(a0, B.x, d2); fma2(a2, B.x, d3); fma2(a4, B.x, d4); fma2(a6, B.x, d5);
        fma2(a1, T.x, d3); fma2(a3, T.x, d4); fma2(a5, T.x, d5);
        u64 d6 = wpair[h + 6];
        fma2(a0, B.y, d3); fma2(a2, B.y, d4); fma2(a4, B.y, d5); fma2(a6, B.y, d6);
        fma2(a1, tfix, d4); fma2(a3, tfix, d5); fma2(a5, tfix, d6);
    }

    // ---- Horizontal add + odd-k n=0 correction ----
    float r0 = hadd2(a0);
    float r1 = hadd2(a1) + f0 * c1;
    float r2 = hadd2(a2);
    float r3 = hadd2(a3) + f0 * c3;
    float r4 = hadd2(a4);
    float r5 = hadd2(a5) + f0 * c5;
    float r6 = hadd2(a6);

    // ---- Normalize and store ----
    const float e0 = cs[NFRAME];
    float* __restrict__ o = out + (size_t)bf * NTAU_OUT + 7 * lane;
    float acc[7] = {r0, r1, r2, r3, r4, r5, r6};
    #pragma unroll
    for (int k = 0; k < 7; k++) {
        float etau = cs[tau0 + k + NFRAME] - cs[tau0 + k];
        o[k] = 2.0f * acc[k] / (e0 + etau + EPS);
    }
}

extern "C" void kernel_launch(void* const* d_in, const int* in_sizes, int n_in,
                              void* d_out, int out_size)
{
    const float* x = (const float*)d_in[0];
    float* out = (float*)d_out;
    (void)in_sizes; (void)n_in; (void)out_size;
    xcorr_kernel<<<32 * FN / WARPS_PER_BLK, 32 * WARPS_PER_BLK>>>(x, out);
}